// round 6
// baseline (speedup 1.0000x reference)
#include <cuda_runtime.h>
#include <cstdint>

#define Bb   8
#define Nn   8192
#define Ss   2048
#define Kk   32
#define Dd   128
#define HIDN 8
#define LEAKY 0.1f
#define NEWXYZ (Bb*3*Ss)   // 49152
#define FLATF 2048          // 256*8

// ---------------- scratch (__device__ globals; no allocation) ----------------
__device__ float4 g_ptsT4[(size_t)Bb*Nn*Dd/4];      // points transposed (B,N,D)  33.5MB
__device__ int    g_knn[(size_t)Bb*Ss*Kk];          // knn indices                 2MB
__device__ float4 g_flat4[(size_t)Bb*Ss*FLATF/4];   // agg flat (B,S,2048)        134MB
__device__ float4 g_wp1[33*128];                    // packed w1 (reordered: pts,dir,pad)
__device__ float4 g_wp2[32*128];
__device__ float4 g_wp3[32*256];
__device__ float4 g_wlinp[512*256];

// ---------------- kernel: copy new_xyz to output ----------------
__global__ void copy_newxyz(const float* __restrict__ xyz, float* __restrict__ out) {
    int i = blockIdx.x * 256 + threadIdx.x;
    if (i >= NEWXYZ) return;
    int s = i & (Ss - 1);
    int c = (i >> 11) % 3;
    int b = i / (3 * Ss);
    out[i] = xyz[((size_t)b * 3 + c) * Nn + s];
}

// ---------------- kernel: transpose points (B,D,N) -> (B,N,D) ----------------
__global__ void transpose_points(const float* __restrict__ pts) {
    __shared__ float tile[32][33];
    float* out = (float*)g_ptsT4;
    int b = blockIdx.z;
    int n0 = blockIdx.x * 32, d0 = blockIdx.y * 32;
    int tx = threadIdx.x, ty = threadIdx.y;  // 32 x 8
    const float* src = pts + (size_t)b * Dd * Nn;
#pragma unroll
    for (int i = 0; i < 32; i += 8)
        tile[ty + i][tx] = src[(size_t)(d0 + ty + i) * Nn + n0 + tx];
    __syncthreads();
    float* dst = out + (size_t)b * Nn * Dd;
#pragma unroll
    for (int i = 0; i < 32; i += 8)
        dst[(size_t)(n0 + ty + i) * Dd + d0 + tx] = tile[tx][ty + i];
}

// ---------------- kernel: pack weights into (c4, o, 4) float4 layout ----------------
// mode 0: direct  mode 1: w1 reorder (smem feats = [points(128), dir(3), pad])
__global__ void pack_weights(float* __restrict__ dst, const float* __restrict__ src,
                             int Cin, int Cout, int C4, int mode) {
    int i = blockIdx.x * 256 + threadIdx.x;
    int total = C4 * Cout * 4;
    if (i >= total) return;
    int j = i & 3;
    int o = (i >> 2) % Cout;
    int c4 = (i >> 2) / Cout;
    int c = c4 * 4 + j;
    float v = 0.f;
    if (mode == 1) {
        if (c < 128)      v = src[o * 131 + 3 + c];
        else if (c < 131) v = src[o * 131 + (c - 128)];
    } else {
        if (c < Cin)      v = src[o * Cin + c];
    }
    dst[i] = v;
}

// ---------------- kernel: KNN (warp per query, jax-stable ordering) ----------------
__global__ void knn_kernel(const float* __restrict__ xyz, int* __restrict__ knn) {
    int warp = threadIdx.x >> 5, lane = threadIdx.x & 31;
    int q = blockIdx.x * 8 + warp;          // 0..16383
    int b = q >> 11;
    int s = q & (Ss - 1);
    const float* xb = xyz + (size_t)b * 3 * Nn;
    float qx = xb[s], qy = xb[Nn + s], qz = xb[2 * Nn + s];
    float qn = qx * qx + qy * qy + qz * qz;

    unsigned long long kept[32];
#pragma unroll
    for (int i = 0; i < 32; ++i) kept[i] = ~0ULL;

    for (int n = lane; n < Nn; n += 32) {
        float px = xb[n], py = xb[Nn + n], pz = xb[2 * Nn + n];
        float pn = px * px + py * py + pz * pz;
        float d = qn + pn - 2.f * (qx * px + qy * py + qz * pz);
        unsigned u = __float_as_uint(d);
        u = (u & 0x80000000u) ? ~u : (u | 0x80000000u);   // order-preserving key
        unsigned long long v = ((unsigned long long)u << 32) | (unsigned)n;
        if (v < kept[31]) {
            kept[31] = v;
#pragma unroll
            for (int j = 31; j > 0; --j) {
                if (kept[j] < kept[j - 1]) {
                    unsigned long long tswap = kept[j]; kept[j] = kept[j - 1]; kept[j - 1] = tswap;
                }
            }
        }
    }
    // merge 32 sorted lane-lists -> global 32 smallest (keys unique: idx in low bits)
    unsigned myidx = 0;
    for (int r = 0; r < 32; ++r) {
        unsigned long long v = kept[0];
#pragma unroll
        for (int off = 16; off; off >>= 1) {
            unsigned long long o = __shfl_xor_sync(0xffffffffu, v, off);
            if (o < v) v = o;
        }
        if (kept[0] == v) {   // unique winner: pop head
#pragma unroll
            for (int j = 0; j < 31; ++j) kept[j] = kept[j + 1];
            kept[31] = ~0ULL;
        }
        if (lane == r) myidx = (unsigned)v;
    }
    knn[(size_t)q * Kk + lane] = (int)myidx;
}

// ---------------- MLP layer: rows in smem, packed weights from L2 ----------------
// 1 broadcast LDS.128 per 4 FFMA: LDS hides inside the FMA-pipe bubble (rt=2),
// so this runs at ~FMA-pipe roofline.
__device__ __forceinline__ void mlp_layer(
    const float* __restrict__ in, int inStride, int C4,
    const float4* __restrict__ wp, int wStride, int obase,
    float* __restrict__ out, int outStride, int t)
{
    int o = obase + (t & 127);
    int rbase = (t >> 7) * 32;
    float acc[32];
#pragma unroll
    for (int i = 0; i < 32; ++i) acc[i] = 0.f;
    for (int c4 = 0; c4 < C4; ++c4) {
        float4 wv = __ldg(&wp[c4 * wStride + o]);
        const float* inc = in + rbase * inStride + 4 * c4;
#pragma unroll
        for (int rr = 0; rr < 32; ++rr) {
            float4 av = *(const float4*)(inc + rr * inStride);   // smem broadcast
            acc[rr] = fmaf(av.x, wv.x, acc[rr]);
            acc[rr] = fmaf(av.y, wv.y, acc[rr]);
            acc[rr] = fmaf(av.z, wv.z, acc[rr]);
            acc[rr] = fmaf(av.w, wv.w, acc[rr]);
        }
    }
#pragma unroll
    for (int rr = 0; rr < 32; ++rr) {
        float v = acc[rr];
        v = v > 0.f ? v : LEAKY * v;
        out[(rbase + rr) * outStride + o] = v;
    }
}

// ---------------- kernel: fused per-neighbor MLP + wnet + aggregation ----------------
// block = 256 threads, handles G=2 queries (64 neighbor rows). smem: A(64x132) B(64x256) wn(64x8)
__global__ __launch_bounds__(256) void pointconv_mlp(
    const float* __restrict__ xyz,
    const float* __restrict__ wn_w1, const float* __restrict__ wn_b1,
    const float* __restrict__ wn_w2, const float* __restrict__ wn_b2,
    const float* __restrict__ wn_w3, const float* __restrict__ wn_b3)
{
    extern __shared__ float sm[];
    float* bufA = sm;                  // 64*132
    float* bufB = sm + 64 * 132;       // 64*256
    float* wnbuf = bufB + 64 * 256;    // 64*8
    const float* ptsT = (const float*)g_ptsT4;
    float* flat = (float*)g_flat4;

    int t = threadIdx.x;
    int q0 = blockIdx.x * 2;
    int b = q0 >> 11;
    int s0 = q0 & (Ss - 1);

    // ---- load feats: [points(128), dir(3), 0] ----
    {
        int r = t >> 2, part = t & 3;      // r 0..63
        int g = r >> 5, k = r & 31;
        int s = s0 + g;
        int idx = __ldg(&g_knn[((size_t)((b << 11) + s)) * Kk + k]);
        const float4* prow = (const float4*)(ptsT + ((size_t)b * Nn + idx) * Dd);
        float4* arow = (float4*)(bufA + r * 132);
#pragma unroll
        for (int jj = 0; jj < 8; ++jj) arow[part * 8 + jj] = __ldg(&prow[part * 8 + jj]);
        if (part == 0) {
            const float* xb = xyz + (size_t)b * 3 * Nn;
            bufA[r * 132 + 128] = xb[idx] - xb[s];
            bufA[r * 132 + 129] = xb[Nn + idx] - xb[Nn + s];
            bufA[r * 132 + 130] = xb[2 * Nn + idx] - xb[2 * Nn + s];
            bufA[r * 132 + 131] = 0.f;
        }
    }
    __syncthreads();

    // ---- weight-net (3->8->8->8 relu) on direction, one thread per row ----
    if (t < 64) {
        float d0 = bufA[t * 132 + 128], d1 = bufA[t * 132 + 129], d2 = bufA[t * 132 + 130];
        float h[8], h2[8];
#pragma unroll
        for (int o = 0; o < 8; ++o) {
            float v = __ldg(&wn_b1[o]) + d0 * __ldg(&wn_w1[o * 3]) +
                      d1 * __ldg(&wn_w1[o * 3 + 1]) + d2 * __ldg(&wn_w1[o * 3 + 2]);
            h[o] = fmaxf(v, 0.f);
        }
#pragma unroll
        for (int o = 0; o < 8; ++o) {
            float v = __ldg(&wn_b2[o]);
#pragma unroll
            for (int c = 0; c < 8; ++c) v = fmaf(h[c], __ldg(&wn_w2[o * 8 + c]), v);
            h2[o] = fmaxf(v, 0.f);
        }
#pragma unroll
        for (int o = 0; o < 8; ++o) {
            float v = __ldg(&wn_b3[o]);
#pragma unroll
            for (int c = 0; c < 8; ++c) v = fmaf(h2[c], __ldg(&wn_w3[o * 8 + c]), v);
            wnbuf[t * 8 + o] = fmaxf(v, 0.f);
        }
    }
    __syncthreads();

    // ---- L1: 132 -> 128 (A -> B) ----
    mlp_layer(bufA, 132, 33, g_wp1, 128, 0, bufB, 256, t);
    __syncthreads();
    // ---- L2: 128 -> 128 (B -> A) ----
    mlp_layer(bufB, 256, 32, g_wp2, 128, 0, bufA, 132, t);
    __syncthreads();
    // ---- L3: 128 -> 256 (A -> B), two output halves ----
    mlp_layer(bufA, 132, 32, g_wp3, 256, 0,   bufB, 256, t);
    mlp_layer(bufA, 132, 32, g_wp3, 256, 128, bufB, 256, t);
    __syncthreads();

    // ---- aggregation: agg[o][h] = sum_k h3[k][o] * w[k][h]; write flat ----
    {
        int o = t;  // 0..255
#pragma unroll
        for (int g = 0; g < 2; ++g) {
            float a[8];
#pragma unroll
            for (int h = 0; h < 8; ++h) a[h] = 0.f;
            for (int k = 0; k < 32; ++k) {
                int r = g * 32 + k;
                float hv = bufB[r * 256 + o];
                float4 w0 = *(const float4*)(wnbuf + r * 8);
                float4 w1v = *(const float4*)(wnbuf + r * 8 + 4);
                a[0] = fmaf(hv, w0.x, a[0]);  a[1] = fmaf(hv, w0.y, a[1]);
                a[2] = fmaf(hv, w0.z, a[2]);  a[3] = fmaf(hv, w0.w, a[3]);
                a[4] = fmaf(hv, w1v.x, a[4]); a[5] = fmaf(hv, w1v.y, a[5]);
                a[6] = fmaf(hv, w1v.z, a[6]); a[7] = fmaf(hv, w1v.w, a[7]);
            }
            int s = s0 + g;
            float4* dst = (float4*)(flat + ((size_t)((b << 11) + s)) * FLATF + o * 8);
            dst[0] = make_float4(a[0], a[1], a[2], a[3]);
            dst[1] = make_float4(a[4], a[5], a[6], a[7]);
        }
    }
}

// ---------------- kernel: final linear 2048 -> 256 + lrelu, transposed output ----------------
// block = 256 threads (one o each), 16 queries per block. smem: 16x2048 floats
__global__ __launch_bounds__(256) void final_linear(float* __restrict__ outbuf) {
    extern __shared__ float sm[];
    const float* flat = (const float*)g_flat4;
    int t = threadIdx.x;
    int s0 = blockIdx.x * 16;          // global query base
    int b = s0 >> 11;
    int sl0 = s0 & (Ss - 1);

    const float4* src = (const float4*)(flat + (size_t)s0 * FLATF);
    float4* dsm = (float4*)sm;
    for (int i = t; i < 16 * (FLATF / 4); i += 256) dsm[i] = __ldg(&src[i]);
    __syncthreads();

    int o = t;
    float acc[16];
#pragma unroll
    for (int i = 0; i < 16; ++i) acc[i] = 0.f;
    for (int f4 = 0; f4 < FLATF / 4; ++f4) {
        float4 wv = __ldg(&g_wlinp[f4 * 256 + o]);
        const float* base = sm + f4 * 4;
#pragma unroll
        for (int ss = 0; ss < 16; ++ss) {
            float4 fv = *(const float4*)(base + ss * FLATF);
            acc[ss] = fmaf(fv.x, wv.x, acc[ss]);
            acc[ss] = fmaf(fv.y, wv.y, acc[ss]);
            acc[ss] = fmaf(fv.z, wv.z, acc[ss]);
            acc[ss] = fmaf(fv.w, wv.w, acc[ss]);
        }
    }
#pragma unroll
    for (int ss = 0; ss < 16; ++ss) {
        float v = acc[ss];
        v = v > 0.f ? v : LEAKY * v;
        outbuf[((size_t)(b * 256 + o)) * Ss + sl0 + ss] = v;
    }
}

// ---------------- launch ----------------
extern "C" void kernel_launch(void* const* d_in, const int* in_sizes, int n_in,
                              void* d_out, int out_size) {
    const float* xyz   = (const float*)d_in[0];
    const float* pts   = (const float*)d_in[1];
    const float* w1    = (const float*)d_in[2];
    const float* w2    = (const float*)d_in[3];
    const float* w3    = (const float*)d_in[4];
    const float* wn_w1 = (const float*)d_in[5];
    const float* wn_b1 = (const float*)d_in[6];
    const float* wn_w2 = (const float*)d_in[7];
    const float* wn_b2 = (const float*)d_in[8];
    const float* wn_w3 = (const float*)d_in[9];
    const float* wn_b3 = (const float*)d_in[10];
    const float* wlin  = (const float*)d_in[11];
    float* out = (float*)d_out;

    cudaFuncSetAttribute(pointconv_mlp, cudaFuncAttributeMaxDynamicSharedMemorySize, 101376);
    cudaFuncSetAttribute(final_linear,  cudaFuncAttributeMaxDynamicSharedMemorySize, 131072);

    // output part 1: new_xyz
    copy_newxyz<<<(NEWXYZ + 255) / 256, 256>>>(xyz, out);

    // prep: transpose points, pack weights
    transpose_points<<<dim3(Nn / 32, Dd / 32, Bb), dim3(32, 8)>>>(pts);

    float* wp1 = nullptr; cudaGetSymbolAddress((void**)&wp1, g_wp1);
    float* wp2 = nullptr; cudaGetSymbolAddress((void**)&wp2, g_wp2);
    float* wp3 = nullptr; cudaGetSymbolAddress((void**)&wp3, g_wp3);
    float* wlp = nullptr; cudaGetSymbolAddress((void**)&wlp, g_wlinp);
    pack_weights<<<(33 * 128 * 4 + 255) / 256, 256>>>(wp1, w1, 131, 128, 33, 1);
    pack_weights<<<(32 * 128 * 4 + 255) / 256, 256>>>(wp2, w2, 128, 128, 32, 0);
    pack_weights<<<(32 * 256 * 4 + 255) / 256, 256>>>(wp3, w3, 128, 256, 32, 0);
    pack_weights<<<(512 * 256 * 4 + 255) / 256, 256>>>(wlp, wlin, 2048, 256, 512, 0);

    // knn
    int* knnp = nullptr; cudaGetSymbolAddress((void**)&knnp, g_knn);
    knn_kernel<<<(Bb * Ss) / 8, 256>>>(xyz, knnp);

    // fused MLP + aggregation
    pointconv_mlp<<<(Bb * Ss) / 2, 256, 101376>>>(xyz, wn_w1, wn_b1, wn_w2, wn_b2, wn_w3, wn_b3);

    // final linear into output part 2
    final_linear<<<(Bb * Ss) / 16, 256, 131072>>>(out + NEWXYZ);
}